// round 1
// baseline (speedup 1.0000x reference)
#include <cuda_runtime.h>
#include <math.h>

#define HW    16384
#define NCH   512
#define NC    16      // classes per group (C)
#define NG    32      // groups (G)
#define NB    8       // batch
#define NPAIR 120     // C*(C-1)/2
#define NBG   256     // NB*NG

// Device-global scratch (no allocations allowed in kernel_launch)
__device__ int   g_chan[NG][NC];     // g_chan[g][c] = channel id (rank-g channel of class c)
__device__ float g_wgt[NG][NC];      // sigmoid(|w|) for that channel
__device__ float g_S[NBG][NPAIR];    // raw Gram partial sums, per (b,g)

// ---------------------------------------------------------------------------
// Kernel A: selection via rank counting (+ zero g_S).
// grid = 16 blocks (one per class), 512 threads (one per channel).
// rank(i) = #{k : w_k > w_i  or (w_k == w_i and k < i)}  -> matches stable
// argsort(-w). If rank < 32, channel i is the rank-th pick of this class.
// ---------------------------------------------------------------------------
__global__ void select_kernel(const float* __restrict__ cw) {
    __shared__ float sw[NCH];
    const int j = blockIdx.x;        // class 0..15
    const int t = threadIdx.x;       // channel 0..511
    const float wi = fabsf(cw[j * NCH + t]);
    sw[t] = wi;
    __syncthreads();

    int rank = 0;
    #pragma unroll 8
    for (int k = 0; k < NCH; k++) {
        const float wk = sw[k];
        rank += (wk > wi) || (wk == wi && k < t);
    }
    if (rank < NG) {
        g_chan[rank][j] = t;
        g_wgt[rank][j]  = 1.0f / (1.0f + expf(-wi));
    }

    // zero the Gram scratch (16 blocks x 512 threads cover 256*120 floats)
    float* S = &g_S[0][0];
    for (int i = blockIdx.x * blockDim.x + t; i < NBG * NPAIR; i += 16 * 512)
        S[i] = 0.0f;
}

// ---------------------------------------------------------------------------
// Kernel B: strict-upper-triangle Gram accumulation.
// grid = 512 blocks: block = (bg, half-of-HW). 256 threads:
//   warps 0-3 (threads 0..127)  -> pairs [0,60)
//   warps 4-7 (threads 128..255)-> pairs [60,120)
// Each half-group covers the whole 4096-float2 chunk. 60 fp32 accumulators
// per thread; float2 loads; weights factored out of the inner loop.
// ---------------------------------------------------------------------------
template <int P0>
__device__ __forceinline__ void run_pairs(const float2* const* rp, int base,
                                          float* __restrict__ acc) {
    for (int it = 0; it < 32; it++) {
        const int i = base + it * 128;
        float2 v[NC];
        #pragma unroll
        for (int c = 0; c < NC; c++) v[c] = __ldg(&rp[c][i]);
        int p = 0;
        #pragma unroll
        for (int c = 0; c < NC; c++) {
            #pragma unroll
            for (int d = c + 1; d < NC; d++) {
                if (p >= P0 && p < P0 + 60) {
                    acc[p - P0] = fmaf(v[c].x, v[d].x,
                                  fmaf(v[c].y, v[d].y, acc[p - P0]));
                }
                p++;
            }
        }
    }
}

__global__ __launch_bounds__(256, 1) void gram_kernel(const float* __restrict__ x) {
    __shared__ float s_part[8][60];   // per-warp reduced partial sums

    const int blk  = blockIdx.x;      // 0..511
    const int half = blk & 1;         // HW half
    const int bg   = blk >> 1;        // 0..255
    const int b    = bg >> 5;
    const int g    = bg & 31;
    const int tid  = threadIdx.x;
    const int warp = tid >> 5;
    const int lane = tid & 31;
    const int grp  = tid >> 7;        // pair half: 0 or 1
    const int lt   = tid & 127;       // lane within half-group

    const float* xb = x + (size_t)(b * NCH) * HW;
    const float2* rp[NC];
    #pragma unroll
    for (int c = 0; c < NC; c++)
        rp[c] = reinterpret_cast<const float2*>(xb + (size_t)g_chan[g][c] * HW);

    float acc[60];
    #pragma unroll
    for (int p = 0; p < 60; p++) acc[p] = 0.0f;

    const int base = half * 4096 + lt;     // float2 index

    if (grp == 0) run_pairs<0 >(rp, base, acc);
    else          run_pairs<60>(rp, base, acc);

    // warp butterfly reduction of all 60 accumulators
    #pragma unroll
    for (int p = 0; p < 60; p++) {
        float v = acc[p];
        v += __shfl_xor_sync(0xffffffffu, v, 16);
        v += __shfl_xor_sync(0xffffffffu, v, 8);
        v += __shfl_xor_sync(0xffffffffu, v, 4);
        v += __shfl_xor_sync(0xffffffffu, v, 2);
        v += __shfl_xor_sync(0xffffffffu, v, 1);
        if (lane == 0) s_part[warp][p] = v;
    }
    __syncthreads();

    // combine 4 warps per pair-half, one global atomic per pair
    if (tid < NPAIR) {
        const int pg = tid / 60;      // which pair half produced this pair
        const int pp = tid % 60;
        const float s = s_part[pg * 4 + 0][pp] + s_part[pg * 4 + 1][pp] +
                        s_part[pg * 4 + 2][pp] + s_part[pg * 4 + 3][pp];
        atomicAdd(&g_S[bg][tid], s);
    }
}

// ---------------------------------------------------------------------------
// Kernel C: weighted |cov| reduction + margin + clamp + batch mean.
// 1 block, 256 threads; thread t handles (b,g) = t.
// ---------------------------------------------------------------------------
__global__ void finalize_kernel(float* __restrict__ out) {
    __shared__ float red[NBG];
    const int t = threadIdx.x;        // bg index
    const int g = t & 31;

    float w[NC];
    #pragma unroll
    for (int c = 0; c < NC; c++) w[c] = g_wgt[g][c];

    float val = 0.0f;
    int p = 0;
    #pragma unroll
    for (int c = 0; c < NC; c++) {
        #pragma unroll
        for (int d = c + 1; d < NC; d++) {
            val += w[c] * w[d] * fabsf(g_S[t][p]);
            p++;
        }
    }
    const float sum_abs_cov = val / (float)(HW - 1);
    const float off_diag    = sum_abs_cov - 60.0f;            // margin = floor(120/2)
    const float loss        = fmaxf(off_diag / 120.0f, 0.0f); // /num_off, clamp(min=0)
    red[t] = loss;
    __syncthreads();

    for (int s = 128; s > 0; s >>= 1) {
        if (t < s) red[t] += red[t + s];
        __syncthreads();
    }
    if (t == 0) out[0] = red[0] / (float)NB;   // sum over groups, mean over batch
}

// ---------------------------------------------------------------------------
extern "C" void kernel_launch(void* const* d_in, const int* in_sizes, int n_in,
                              void* d_out, int out_size) {
    (void)in_sizes; (void)n_in; (void)out_size;
    const float* x  = (const float*)d_in[0];   // [8,512,128,128] fp32
    const float* cw = (const float*)d_in[1];   // [19,512] fp32

    select_kernel<<<16, 512>>>(cw);
    gram_kernel<<<512, 256>>>(x);
    finalize_kernel<<<1, 256>>>((float*)d_out);
}

// round 2
// speedup vs baseline: 1.0353x; 1.0353x over previous
#include <cuda_runtime.h>
#include <math.h>

#define HW     16384
#define NCH    512
#define NC     16       // classes per group (C)
#define NG     32       // groups (G)
#define NB     8        // batch
#define NPAIR  120      // C*(C-1)/2
#define NBG    256      // NB*NG
#define QTR    4096     // floats per channel per quarter of HW
#define TILE   256      // floats per channel per pipeline tile
#define NT     (QTR / TILE)   // 16 tiles per quarter
#define STAGES 3

// Device-global scratch (no allocations allowed)
__device__ int   g_chan[NG][NC];          // channel id: rank-g pick of class c
__device__ float g_wgt[NG][NC];           // sigmoid(|w|) of that pick
__device__ float g_S4[NBG][4][NPAIR];     // per-quarter raw Gram partials

// ---------------------------------------------------------------------------
// Kernel A: selection via rank counting.
// grid = (16 classes, 4 channel-chunks), 512 threads.
// Thread layout: 128 channels x 4 compare-slices; shfl-reduce the 4 slices.
// rank(i) = #{k : w_k > w_i or (w_k == w_i and k < i)} -> stable argsort(-w).
// ---------------------------------------------------------------------------
__global__ void select_kernel(const float* __restrict__ cw) {
    __shared__ float sw[NCH];
    const int j   = blockIdx.x;          // class
    const int q   = blockIdx.y;          // channel chunk
    const int tid = threadIdx.x;
    sw[tid] = fabsf(cw[j * NCH + tid]);
    __syncthreads();

    const int chl = tid >> 2;            // 0..127 channel-in-chunk
    const int sl  = tid & 3;             // compare slice
    const int i   = q * 128 + chl;       // global channel
    const float wi = sw[i];

    int r = 0;
    const int k0 = sl * 128;
    #pragma unroll 8
    for (int k = k0; k < k0 + 128; k++) {
        const float wk = sw[k];
        r += (wk > wi) || (wk == wi && k < i);
    }
    // the 4 slices of one channel are lanes differing in bits 0-1
    r += __shfl_xor_sync(0xffffffffu, r, 1);
    r += __shfl_xor_sync(0xffffffffu, r, 2);

    if (sl == 0 && r < NG) {
        g_chan[r][j] = i;
        g_wgt[r][j]  = 1.0f / (1.0f + expf(-wi));
    }
}

// ---------------------------------------------------------------------------
// Kernel B: Gram accumulation, cp.async 3-stage smem pipeline.
// grid = 1024 blocks = (bg 0..255) x (quarter 0..3); 256 threads.
//   loader role:  thread = (channel mc = tid>>4, slot ms = tid&15),
//                 4x cp.async.cg 16B per tile  (16KB tile, read ONCE).
//   compute role: grp = tid>>7 picks pair-half [0,60) or [60,120);
//                 lt = tid&127 picks the float2 position inside the tile.
// ---------------------------------------------------------------------------
template <int P0>
__device__ __forceinline__ void do_pairs(const float2* __restrict__ v,
                                         float* __restrict__ acc) {
    int p = 0;
    #pragma unroll
    for (int c = 0; c < NC; c++) {
        #pragma unroll
        for (int d = c + 1; d < NC; d++) {
            if (p >= P0 && p < P0 + 60) {
                acc[p - P0] = fmaf(v[c].x, v[d].x,
                              fmaf(v[c].y, v[d].y, acc[p - P0]));
            }
            p++;
        }
    }
}

__global__ __launch_bounds__(256, 2) void gram_kernel(const float* __restrict__ x) {
    __shared__ __align__(16) float s_buf[STAGES][NC][TILE];   // 48 KB

    const int bid = blockIdx.x;
    const int q   = bid & 3;
    const int bg  = bid >> 2;
    const int b   = bg >> 5;
    const int g   = bg & 31;
    const int tid = threadIdx.x;

    // loader role
    const int mc = tid >> 4;             // channel this thread feeds
    const int ms = tid & 15;             // float4 slot
    const float* src = x + ((size_t)(b * NCH + g_chan[g][mc])) * HW + q * QTR;

    // compute role
    const int grp  = tid >> 7;
    const int lt   = tid & 127;
    const int warp = tid >> 5;
    const int lane = tid & 31;

    auto issue = [&](int stage, int t) {
        const float4* gp = reinterpret_cast<const float4*>(src + t * TILE) + ms;
        float4* sp = reinterpret_cast<float4*>(&s_buf[stage][mc][0]) + ms;
        #pragma unroll
        for (int k = 0; k < 4; k++) {
            unsigned saddr = (unsigned)__cvta_generic_to_shared(sp + 16 * k);
            asm volatile("cp.async.cg.shared.global [%0], [%1], 16;\n"
                         :: "r"(saddr), "l"(gp + 16 * k) : "memory");
        }
    };

    float acc[60];
    #pragma unroll
    for (int p = 0; p < 60; p++) acc[p] = 0.0f;

    // prologue: 2 tiles in flight
    issue(0, 0); asm volatile("cp.async.commit_group;" ::: "memory");
    issue(1, 1); asm volatile("cp.async.commit_group;" ::: "memory");

    for (int t = 0; t < NT; t++) {
        __syncthreads();   // everyone done reading the stage we're about to fill
        if (t + 2 < NT) issue((t + 2) % STAGES, t + 2);
        asm volatile("cp.async.commit_group;" ::: "memory");
        asm volatile("cp.async.wait_group 2;" ::: "memory");  // tile t landed
        __syncthreads();

        const float2* sm = reinterpret_cast<const float2*>(&s_buf[t % STAGES][0][0]);
        float2 v[NC];
        #pragma unroll
        for (int c = 0; c < NC; c++) v[c] = sm[c * (TILE / 2) + lt];

        if (grp == 0) do_pairs<0 >(v, acc);
        else          do_pairs<60>(v, acc);
    }

    // drain any残 groups before reusing smem
    asm volatile("cp.async.wait_group 0;" ::: "memory");
    __syncthreads();

    // reuse the tile buffer for cross-warp partials
    float* s_part = &s_buf[0][0][0];     // [8][60]
    #pragma unroll
    for (int p = 0; p < 60; p++) {
        float vv = acc[p];
        vv += __shfl_xor_sync(0xffffffffu, vv, 16);
        vv += __shfl_xor_sync(0xffffffffu, vv, 8);
        vv += __shfl_xor_sync(0xffffffffu, vv, 4);
        vv += __shfl_xor_sync(0xffffffffu, vv, 2);
        vv += __shfl_xor_sync(0xffffffffu, vv, 1);
        if (lane == 0) s_part[warp * 60 + p] = vv;
    }
    __syncthreads();

    if (tid < NPAIR) {
        const int pg = tid / 60;
        const int pp = tid % 60;
        g_S4[bg][q][tid] = s_part[(pg * 4 + 0) * 60 + pp] +
                           s_part[(pg * 4 + 1) * 60 + pp] +
                           s_part[(pg * 4 + 2) * 60 + pp] +
                           s_part[(pg * 4 + 3) * 60 + pp];
    }
}

// ---------------------------------------------------------------------------
// Kernel C: weighted |cov| reduction + margin + clamp + batch mean.
// ---------------------------------------------------------------------------
__global__ void finalize_kernel(float* __restrict__ out) {
    __shared__ float red[NBG];
    const int t = threadIdx.x;           // bg index
    const int g = t & 31;

    float w[NC];
    #pragma unroll
    for (int c = 0; c < NC; c++) w[c] = g_wgt[g][c];

    float val = 0.0f;
    int p = 0;
    #pragma unroll
    for (int c = 0; c < NC; c++) {
        #pragma unroll
        for (int d = c + 1; d < NC; d++) {
            const float S = g_S4[t][0][p] + g_S4[t][1][p] +
                            g_S4[t][2][p] + g_S4[t][3][p];
            val += w[c] * w[d] * fabsf(S);
            p++;
        }
    }
    const float sum_abs_cov = val / (float)(HW - 1);
    const float off_diag    = sum_abs_cov - 60.0f;            // margin = floor(120/2)
    const float loss        = fmaxf(off_diag / 120.0f, 0.0f);
    red[t] = loss;
    __syncthreads();

    for (int s = 128; s > 0; s >>= 1) {
        if (t < s) red[t] += red[t + s];
        __syncthreads();
    }
    if (t == 0) out[0] = red[0] / (float)NB;
}

// ---------------------------------------------------------------------------
extern "C" void kernel_launch(void* const* d_in, const int* in_sizes, int n_in,
                              void* d_out, int out_size) {
    (void)in_sizes; (void)n_in; (void)out_size;
    const float* x  = (const float*)d_in[0];   // [8,512,128,128] fp32
    const float* cw = (const float*)d_in[1];   // [19,512] fp32

    select_kernel<<<dim3(16, 4), 512>>>(cw);
    gram_kernel<<<1024, 256>>>(x);
    finalize_kernel<<<1, 256>>>((float*)d_out);
}